// round 1
// baseline (speedup 1.0000x reference)
#include <cuda_runtime.h>
#include <cstdint>

#define DIMN 1024
#define SEQ 2048
#define BATCH 4
#define HEADS 16
#define HD 64
#define MTOT (BATCH*SEQ)

// ---------------- scratch (static device arrays; no allocation) ----------------
__device__ float g_q[(size_t)MTOT * DIMN];
__device__ float g_k[(size_t)MTOT * DIMN];
__device__ float g_v[(size_t)MTOT * DIMN];
__device__ float g_o[(size_t)MTOT * DIMN];

// ---------------- helpers ----------------
__device__ __forceinline__ uint32_t tf32_rna(float x) {
    uint32_t r;
    asm("cvt.rna.tf32.f32 %0, %1;" : "=r"(r) : "f"(x));
    return r;
}

// split fp32 into hi (tf32) + lo (tf32 of residual); hi+lo ~ fp32 precision
__device__ __forceinline__ void split_tf32(float x, uint32_t& hi, uint32_t& lo) {
    hi = tf32_rna(x);
    float hif = __uint_as_float(hi);
    lo = tf32_rna(x - hif);
}

__device__ __forceinline__ void mma_tf32(float* c, const uint32_t* a, uint32_t b0, uint32_t b1) {
    asm volatile(
        "mma.sync.aligned.m16n8k8.row.col.f32.tf32.tf32.f32 "
        "{%0,%1,%2,%3}, {%4,%5,%6,%7}, {%8,%9}, {%0,%1,%2,%3};"
        : "+f"(c[0]), "+f"(c[1]), "+f"(c[2]), "+f"(c[3])
        : "r"(a[0]), "r"(a[1]), "r"(a[2]), "r"(a[3]), "r"(b0), "r"(b1));
}

__device__ __forceinline__ float ex2f(float x) {
    float y;
    asm("ex2.approx.f32 %0, %1;" : "=f"(y) : "f"(x));
    return y;
}

// ---------------- GEMM + bias: C[M,1024] = A[M,1024] @ W[1024,1024] + b ----------------
// Block tile 128x128, BK=16, 256 threads (8 warps, each 64x32), 3xTF32 split.
#define SA_LD 20
#define SB_LD 136

__global__ __launch_bounds__(256, 2)
void gemm_bias_k(const float* __restrict__ A, const float* __restrict__ W,
                 const float* __restrict__ bias, float* __restrict__ C)
{
    __shared__ float sAhi[128 * SA_LD], sAlo[128 * SA_LD];
    __shared__ float sBhi[16 * SB_LD],  sBlo[16 * SB_LD];

    const int t = threadIdx.x;
    const int w = t >> 5, lane = t & 31, gid = lane >> 2, tig = lane & 3;
    const int wm = w & 1, wn = w >> 1;
    const int mb = blockIdx.y, nb = blockIdx.x;

    float acc[4][4][4];
#pragma unroll
    for (int i = 0; i < 4; i++)
#pragma unroll
        for (int j = 0; j < 4; j++)
#pragma unroll
            for (int r = 0; r < 4; r++) acc[i][j][r] = 0.f;

    for (int kt = 0; kt < 64; kt++) {
        __syncthreads();
#pragma unroll
        for (int j = 0; j < 2; j++) {
            int i = t + j * 256;
            // A tile: 128 rows x 16 cols
            {
                int row = i >> 2, c4 = i & 3;
                float4 va = *(const float4*)(A + (size_t)(mb * 128 + row) * DIMN + kt * 16 + c4 * 4);
                float xs[4] = {va.x, va.y, va.z, va.w};
                int base = row * SA_LD + c4 * 4;
#pragma unroll
                for (int e = 0; e < 4; e++) {
                    uint32_t hb, lb;
                    split_tf32(xs[e], hb, lb);
                    sAhi[base + e] = __uint_as_float(hb);
                    sAlo[base + e] = __uint_as_float(lb);
                }
            }
            // W tile: 16 rows x 128 cols
            {
                int row = i >> 5, c4 = i & 31;
                float4 vb = *(const float4*)(W + (size_t)(kt * 16 + row) * DIMN + nb * 128 + c4 * 4);
                float ys[4] = {vb.x, vb.y, vb.z, vb.w};
                int base = row * SB_LD + c4 * 4;
#pragma unroll
                for (int e = 0; e < 4; e++) {
                    uint32_t hb, lb;
                    split_tf32(ys[e], hb, lb);
                    sBhi[base + e] = __uint_as_float(hb);
                    sBlo[base + e] = __uint_as_float(lb);
                }
            }
        }
        __syncthreads();

#pragma unroll
        for (int ks = 0; ks < 2; ks++) {
#pragma unroll
            for (int mt = 0; mt < 4; mt++) {
                const int r0 = wm * 64 + mt * 16 + gid;
                const int cc = ks * 8 + tig;
                uint32_t ah[4], al[4];
                ah[0] = __float_as_uint(sAhi[r0 * SA_LD + cc]);
                ah[1] = __float_as_uint(sAhi[(r0 + 8) * SA_LD + cc]);
                ah[2] = __float_as_uint(sAhi[r0 * SA_LD + cc + 4]);
                ah[3] = __float_as_uint(sAhi[(r0 + 8) * SA_LD + cc + 4]);
                al[0] = __float_as_uint(sAlo[r0 * SA_LD + cc]);
                al[1] = __float_as_uint(sAlo[(r0 + 8) * SA_LD + cc]);
                al[2] = __float_as_uint(sAlo[r0 * SA_LD + cc + 4]);
                al[3] = __float_as_uint(sAlo[(r0 + 8) * SA_LD + cc + 4]);
#pragma unroll
                for (int nt = 0; nt < 4; nt++) {
                    const int cn = wn * 32 + nt * 8 + gid;
                    uint32_t b0h = __float_as_uint(sBhi[(ks * 8 + tig) * SB_LD + cn]);
                    uint32_t b1h = __float_as_uint(sBhi[(ks * 8 + tig + 4) * SB_LD + cn]);
                    uint32_t b0l = __float_as_uint(sBlo[(ks * 8 + tig) * SB_LD + cn]);
                    uint32_t b1l = __float_as_uint(sBlo[(ks * 8 + tig + 4) * SB_LD + cn]);
                    mma_tf32(acc[mt][nt], ah, b0h, b1h);
                    mma_tf32(acc[mt][nt], ah, b0l, b1l);
                    mma_tf32(acc[mt][nt], al, b0h, b1h);
                }
            }
        }
    }

    // epilogue: + bias, write C
#pragma unroll
    for (int mt = 0; mt < 4; mt++) {
        const int r0 = mb * 128 + wm * 64 + mt * 16 + gid;
#pragma unroll
        for (int nt = 0; nt < 4; nt++) {
            const int cc = nb * 128 + wn * 32 + nt * 8 + 2 * tig;
            const float b0 = bias[cc], b1 = bias[cc + 1];
            C[(size_t)r0 * DIMN + cc]         = acc[mt][nt][0] + b0;
            C[(size_t)r0 * DIMN + cc + 1]     = acc[mt][nt][1] + b1;
            C[(size_t)(r0 + 8) * DIMN + cc]     = acc[mt][nt][2] + b0;
            C[(size_t)(r0 + 8) * DIMN + cc + 1] = acc[mt][nt][3] + b1;
        }
    }
}

// ---------------- flash attention ----------------
// grid (S/64, H, B), 128 threads (4 warps). Each warp: 16 query rows x hd=64.
__global__ __launch_bounds__(128)
void attn_k(const float* __restrict__ q, const float* __restrict__ kk,
            const float* __restrict__ vv, float* __restrict__ o)
{
    __shared__ float sK[64 * 68];   // [key][dim]
    __shared__ float sVT[64 * 68];  // [dim][key]

    const int t = threadIdx.x;
    const int w = t >> 5, lane = t & 31, gid = lane >> 2, tig = lane & 3;
    const int qt = blockIdx.x, h = blockIdx.y, b = blockIdx.z;

    const float* qb = q  + (size_t)b * SEQ * DIMN + h * HD;
    const float* kb = kk + (size_t)b * SEQ * DIMN + h * HD;
    const float* vb = vv + (size_t)b * SEQ * DIMN + h * HD;
    float*       ob = o  + (size_t)b * SEQ * DIMN + h * HD;

    const int r0 = qt * 64 + w * 16 + gid;  // query row (lower of pair)

    // Q fragments, pre-scaled by 1/sqrt(hd)=0.125, split hi/lo, in registers
    uint32_t qhi[8][4], qlo[8][4];
#pragma unroll
    for (int ks = 0; ks < 8; ks++) {
        const int c0 = ks * 8 + tig;
        float x0 = qb[(size_t)r0 * DIMN + c0] * 0.125f;
        float x1 = qb[(size_t)(r0 + 8) * DIMN + c0] * 0.125f;
        float x2 = qb[(size_t)r0 * DIMN + c0 + 4] * 0.125f;
        float x3 = qb[(size_t)(r0 + 8) * DIMN + c0 + 4] * 0.125f;
        split_tf32(x0, qhi[ks][0], qlo[ks][0]);
        split_tf32(x1, qhi[ks][1], qlo[ks][1]);
        split_tf32(x2, qhi[ks][2], qlo[ks][2]);
        split_tf32(x3, qhi[ks][3], qlo[ks][3]);
    }

    float oAcc[8][4];
#pragma unroll
    for (int i = 0; i < 8; i++)
#pragma unroll
        for (int r = 0; r < 4; r++) oAcc[i][r] = 0.f;

    float m0 = -1e30f, m1 = -1e30f, l0 = 0.f, l1 = 0.f;
    const float L2E = 1.4426950408889634f;

    for (int kt = 0; kt < 32; kt++) {
        __syncthreads();
        // load K tile [64x64] and V tile (transposed) into smem
#pragma unroll
        for (int j = 0; j < 8; j++) {
            int i = j * 128 + t;
            int row = i >> 4, c4 = i & 15;
            float4 kv = *(const float4*)(kb + (size_t)(kt * 64 + row) * DIMN + c4 * 4);
            *(float4*)&sK[row * 68 + c4 * 4] = kv;
            float4 vx = *(const float4*)(vb + (size_t)(kt * 64 + row) * DIMN + c4 * 4);
            sVT[(c4 * 4 + 0) * 68 + row] = vx.x;
            sVT[(c4 * 4 + 1) * 68 + row] = vx.y;
            sVT[(c4 * 4 + 2) * 68 + row] = vx.z;
            sVT[(c4 * 4 + 3) * 68 + row] = vx.w;
        }
        __syncthreads();

        // S = Q @ K^T (scaled), 16x64 per warp
        float sAcc[8][4];
#pragma unroll
        for (int i = 0; i < 8; i++)
#pragma unroll
            for (int r = 0; r < 4; r++) sAcc[i][r] = 0.f;

#pragma unroll
        for (int nt = 0; nt < 8; nt++) {
#pragma unroll
            for (int ks = 0; ks < 8; ks++) {
                const int kcol = ks * 8 + tig;
                const int nrow = nt * 8 + gid;
                float b0f = sK[nrow * 68 + kcol];
                float b1f = sK[nrow * 68 + kcol + 4];
                uint32_t b0h, b0l, b1h, b1l;
                split_tf32(b0f, b0h, b0l);
                split_tf32(b1f, b1h, b1l);
                mma_tf32(sAcc[nt], qhi[ks], b0h, b1h);
                mma_tf32(sAcc[nt], qhi[ks], b0l, b1l);
                mma_tf32(sAcc[nt], qlo[ks], b0h, b1h);
            }
        }

        // online softmax (rows r0 -> frag regs 0,1 ; rows r0+8 -> frag regs 2,3)
        float rm0 = -1e30f, rm1 = -1e30f;
#pragma unroll
        for (int nt = 0; nt < 8; nt++) {
            rm0 = fmaxf(rm0, fmaxf(sAcc[nt][0], sAcc[nt][1]));
            rm1 = fmaxf(rm1, fmaxf(sAcc[nt][2], sAcc[nt][3]));
        }
        rm0 = fmaxf(rm0, __shfl_xor_sync(0xffffffffu, rm0, 1));
        rm0 = fmaxf(rm0, __shfl_xor_sync(0xffffffffu, rm0, 2));
        rm1 = fmaxf(rm1, __shfl_xor_sync(0xffffffffu, rm1, 1));
        rm1 = fmaxf(rm1, __shfl_xor_sync(0xffffffffu, rm1, 2));

        float m0n = fmaxf(m0, rm0), m1n = fmaxf(m1, rm1);
        float al0 = ex2f((m0 - m0n) * L2E);
        float al1 = ex2f((m1 - m1n) * L2E);
        m0 = m0n; m1 = m1n;

        float rs0 = 0.f, rs1 = 0.f;
#pragma unroll
        for (int nt = 0; nt < 8; nt++) {
            sAcc[nt][0] = ex2f((sAcc[nt][0] - m0) * L2E);
            sAcc[nt][1] = ex2f((sAcc[nt][1] - m0) * L2E);
            sAcc[nt][2] = ex2f((sAcc[nt][2] - m1) * L2E);
            sAcc[nt][3] = ex2f((sAcc[nt][3] - m1) * L2E);
            rs0 += sAcc[nt][0] + sAcc[nt][1];
            rs1 += sAcc[nt][2] + sAcc[nt][3];
        }
        rs0 += __shfl_xor_sync(0xffffffffu, rs0, 1);
        rs0 += __shfl_xor_sync(0xffffffffu, rs0, 2);
        rs1 += __shfl_xor_sync(0xffffffffu, rs1, 1);
        rs1 += __shfl_xor_sync(0xffffffffu, rs1, 2);

        l0 = l0 * al0 + rs0;
        l1 = l1 * al1 + rs1;
#pragma unroll
        for (int nt = 0; nt < 8; nt++) {
            oAcc[nt][0] *= al0; oAcc[nt][1] *= al0;
            oAcc[nt][2] *= al1; oAcc[nt][3] *= al1;
        }

        // O += P @ V : P C-fragments -> A-fragments via lane shuffles
#pragma unroll
        for (int ks = 0; ks < 8; ks++) {
            const int src0 = gid * 4 + (tig >> 1);
            const int src2 = src0 + 2;
            const bool odd = tig & 1;
            float p00 = __shfl_sync(0xffffffffu, sAcc[ks][0], src0);
            float p01 = __shfl_sync(0xffffffffu, sAcc[ks][1], src0);
            float a0f = odd ? p01 : p00;
            float p02 = __shfl_sync(0xffffffffu, sAcc[ks][0], src2);
            float p03 = __shfl_sync(0xffffffffu, sAcc[ks][1], src2);
            float a2f = odd ? p03 : p02;
            float p10 = __shfl_sync(0xffffffffu, sAcc[ks][2], src0);
            float p11 = __shfl_sync(0xffffffffu, sAcc[ks][3], src0);
            float a1f = odd ? p11 : p10;
            float p12 = __shfl_sync(0xffffffffu, sAcc[ks][2], src2);
            float p13 = __shfl_sync(0xffffffffu, sAcc[ks][3], src2);
            float a3f = odd ? p13 : p12;

            uint32_t ah[4], al[4];
            split_tf32(a0f, ah[0], al[0]);
            split_tf32(a1f, ah[1], al[1]);
            split_tf32(a2f, ah[2], al[2]);
            split_tf32(a3f, ah[3], al[3]);

#pragma unroll
            for (int nt = 0; nt < 8; nt++) {
                const int dd = nt * 8 + gid;
                const int kc = ks * 8 + tig;
                float b0f = sVT[dd * 68 + kc];
                float b1f = sVT[dd * 68 + kc + 4];
                uint32_t b0h, b0l, b1h, b1l;
                split_tf32(b0f, b0h, b0l);
                split_tf32(b1f, b1h, b1l);
                mma_tf32(oAcc[nt], ah, b0h, b1h);
                mma_tf32(oAcc[nt], ah, b0l, b1l);
                mma_tf32(oAcc[nt], al, b0h, b1h);
            }
        }
    }

    const float inv0 = 1.f / l0, inv1 = 1.f / l1;
#pragma unroll
    for (int nt = 0; nt < 8; nt++) {
        const int cc = nt * 8 + 2 * tig;
        ob[(size_t)r0 * DIMN + cc]         = oAcc[nt][0] * inv0;
        ob[(size_t)r0 * DIMN + cc + 1]     = oAcc[nt][1] * inv0;
        ob[(size_t)(r0 + 8) * DIMN + cc]     = oAcc[nt][2] * inv1;
        ob[(size_t)(r0 + 8) * DIMN + cc + 1] = oAcc[nt][3] * inv1;
    }
}

// ---------------- launch ----------------
extern "C" void kernel_launch(void* const* d_in, const int* in_sizes, int n_in,
                              void* d_out, int out_size)
{
    const float* Q  = (const float*)d_in[0];
    const float* K  = (const float*)d_in[1];
    const float* V  = (const float*)d_in[2];
    const float* Wq = (const float*)d_in[3];
    const float* bq = (const float*)d_in[4];
    const float* Wk = (const float*)d_in[5];
    const float* bk = (const float*)d_in[6];
    const float* Wv = (const float*)d_in[7];
    const float* bv = (const float*)d_in[8];
    const float* Wo = (const float*)d_in[9];
    const float* bo = (const float*)d_in[10];
    float* out = (float*)d_out;

    float *gq = nullptr, *gk = nullptr, *gv = nullptr, *go = nullptr;
    cudaGetSymbolAddress((void**)&gq, g_q);
    cudaGetSymbolAddress((void**)&gk, g_k);
    cudaGetSymbolAddress((void**)&gv, g_v);
    cudaGetSymbolAddress((void**)&go, g_o);

    dim3 gg(8, 64);
    gemm_bias_k<<<gg, 256>>>(Q, Wq, bq, gq);
    gemm_bias_k<<<gg, 256>>>(K, Wk, bk, gk);
    gemm_bias_k<<<gg, 256>>>(V, Wv, bv, gv);
    attn_k<<<dim3(SEQ / 64, HEADS, BATCH), 128>>>(gq, gk, gv, go);
    gemm_bias_k<<<gg, 256>>>(go, Wo, bo, out);
}

// round 3
// speedup vs baseline: 2.7018x; 2.7018x over previous
#include <cuda_runtime.h>
#include <cstdint>
#include <cstddef>

#define DIMN 1024
#define SEQ  2048
#define BATCH 4
#define HEADS 16
#define HD 64
#define MTOT (BATCH*SEQ)

typedef unsigned int u32;
typedef unsigned short u16;

#define NELEM ((size_t)MTOT*DIMN)
#define WELEM ((size_t)DIMN*DIMN)

// ---------------- static scratch (no allocation) ----------------
__device__ u16 inQh[NELEM], inQl[NELEM], inKh[NELEM], inKl[NELEM], inVh[NELEM], inVl[NELEM];
__device__ u16 wQh[WELEM], wQl[WELEM], wKh[WELEM], wKl[WELEM];
__device__ u16 wVh[WELEM], wVl[WELEM], wOh[WELEM], wOl[WELEM];
__device__ u16 pjQh[NELEM], pjQl[NELEM], pjKh[NELEM], pjKl[NELEM], pjVh[NELEM], pjVl[NELEM];
__device__ u16 aOh[NELEM], aOl[NELEM];

// ---------------- helpers ----------------
// pack: x0 -> low half, x1 -> high half
__device__ __forceinline__ u32 packbf2(float x0, float x1){
    u32 d; asm("cvt.rn.bf16x2.f32 %0, %1, %2;" : "=r"(d) : "f"(x1), "f"(x0)); return d;
}
__device__ __forceinline__ void split2(float x0, float x1, u32 &h, u32 &l){
    h = packbf2(x0, x1);
    float h0 = __uint_as_float(h << 16);
    float h1 = __uint_as_float(h & 0xFFFF0000u);
    l = packbf2(x0 - h0, x1 - h1);
}
__device__ __forceinline__ void ldsm4(u32 r[4], u32 a){
    asm volatile("ldmatrix.sync.aligned.m8n8.x4.shared.b16 {%0,%1,%2,%3}, [%4];"
                 : "=r"(r[0]),"=r"(r[1]),"=r"(r[2]),"=r"(r[3]) : "r"(a));
}
__device__ __forceinline__ void ldsm4t(u32 r[4], u32 a){
    asm volatile("ldmatrix.sync.aligned.m8n8.x4.trans.shared.b16 {%0,%1,%2,%3}, [%4];"
                 : "=r"(r[0]),"=r"(r[1]),"=r"(r[2]),"=r"(r[3]) : "r"(a));
}
__device__ __forceinline__ void mmabf(float c[4], const u32 a[4], u32 b0, u32 b1){
    asm volatile("mma.sync.aligned.m16n8k16.row.col.f32.bf16.bf16.f32 "
        "{%0,%1,%2,%3}, {%4,%5,%6,%7}, {%8,%9}, {%0,%1,%2,%3};"
        : "+f"(c[0]),"+f"(c[1]),"+f"(c[2]),"+f"(c[3])
        : "r"(a[0]),"r"(a[1]),"r"(a[2]),"r"(a[3]), "r"(b0),"r"(b1));
}
__device__ __forceinline__ void cpa16(u32 dst, const void* src){
    asm volatile("cp.async.cg.shared.global [%0], [%1], 16;" :: "r"(dst), "l"(src));
}
__device__ __forceinline__ void cpcommit(){ asm volatile("cp.async.commit_group;"); }
__device__ __forceinline__ void cpwait1(){ asm volatile("cp.async.wait_group 1;"); }
__device__ __forceinline__ void cpwait0(){ asm volatile("cp.async.wait_group 0;"); }
__device__ __forceinline__ float ex2f(float x){ float y; asm("ex2.approx.f32 %0, %1;" : "=f"(y) : "f"(x)); return y; }
__device__ __forceinline__ u32 smaddr(const void* p){
    u32 a; asm("{ .reg .u64 t; cvta.to.shared.u64 t, %1; cvt.u32.u64 %0, t; }" : "=r"(a) : "l"(p)); return a;
}

// ---------------- split: fp32 -> bf16 hi/lo ----------------
__global__ void split_k(const float* __restrict__ x, u16* __restrict__ hi,
                        u16* __restrict__ lo, int n4)
{
    int i = blockIdx.x * blockDim.x + threadIdx.x;
    if (i < n4){
        float4 v = ((const float4*)x)[i];
        u32 h0, l0, h1, l1;
        split2(v.x, v.y, h0, l0);
        split2(v.z, v.w, h1, l1);
        ((uint2*)hi)[i] = make_uint2(h0, h1);
        ((uint2*)lo)[i] = make_uint2(l0, l1);
    }
}

// ---------------- GEMM+bias, bf16 2-split, 128x128x32 tiles, 256 thr ----------------
// smem per buffer: A[128 rows][128B: hi 4 chunks | lo 4 chunks], B[32 rows][512B: hi 16 | lo 16]
// swizzle: chunk ^= (row & 7)
__global__ __launch_bounds__(256)
void gemm_bias_k(const u16* __restrict__ Ah, const u16* __restrict__ Al,
                 const u16* __restrict__ Bh, const u16* __restrict__ Bl,
                 const float* __restrict__ bias,
                 u16* __restrict__ Ch, u16* __restrict__ Cl, float* __restrict__ Cf)
{
    extern __shared__ char sm[];
    const u32 smBase = smaddr(sm);
    const int t = threadIdx.x;
    const int w = t >> 5, lane = t & 31, gid = lane >> 2, tig = lane & 3;
    const int wm = w & 1, wn = w >> 1;
    const int nb = blockIdx.x, mb = blockIdx.y;

    float acc[4][4][4];
#pragma unroll
    for (int i = 0; i < 4; i++)
#pragma unroll
        for (int j = 0; j < 4; j++)
#pragma unroll
            for (int r = 0; r < 4; r++) acc[i][j][r] = 0.f;

    auto loadTile = [&](int kt, int buf){
        u32 bufA = smBase + buf * 32768;
        u32 bufB = bufA + 16384;
#pragma unroll
        for (int j = 0; j < 4; j++){
            int id = t + 256 * j;
            int row = id >> 3, c = id & 7;
            const u16* src = (c < 4 ? Ah : Al) + (size_t)(mb*128 + row)*DIMN + kt*32 + (c&3)*8;
            cpa16(bufA + row*128 + ((c ^ (row&7)) << 4), src);
        }
#pragma unroll
        for (int j = 0; j < 4; j++){
            int id = t + 256 * j;
            int row = id >> 5, c = id & 31;
            const u16* src = (c < 16 ? Bh : Bl) + (size_t)(kt*32 + row)*DIMN + nb*128 + (c&15)*8;
            cpa16(bufB + row*512 + ((c ^ (row&7)) << 4), src);
        }
    };

    loadTile(0, 0); cpcommit();

    for (int kt = 0; kt < 32; kt++){
        int buf = kt & 1;
        if (kt < 31){ loadTile(kt+1, buf^1); cpcommit(); cpwait1(); }
        else cpwait0();
        __syncthreads();

        u32 bufA = smBase + buf * 32768;
        u32 bufB = bufA + 16384;
#pragma unroll
        for (int ks = 0; ks < 2; ks++){
            u32 ah[4][4], al[4][4];
#pragma unroll
            for (int mt = 0; mt < 4; mt++){
                u32 rowA = wm*64 + mt*16 + (lane & 15);
                u32 ch = ks*2 + ((lane >> 4) & 1);
                ldsm4(ah[mt], bufA + rowA*128 + ((ch ^ (rowA&7)) << 4));
                ldsm4(al[mt], bufA + rowA*128 + (((ch+4) ^ (rowA&7)) << 4));
            }
#pragma unroll
            for (int nb16 = 0; nb16 < 2; nb16++){
                u32 rowB = ks*16 + ((lane >> 3) & 1)*8 + (lane & 7);
                u32 cb = wn*4 + nb16*2 + ((lane >> 4) & 1);
                u32 bh[4], bl[4];
                ldsm4t(bh, bufB + rowB*512 + ((cb ^ (rowB&7)) << 4));
                ldsm4t(bl, bufB + rowB*512 + (((cb+16) ^ (rowB&7)) << 4));
#pragma unroll
                for (int mt = 0; mt < 4; mt++){
                    mmabf(acc[mt][nb16*2],   ah[mt], bh[0], bh[1]);
                    mmabf(acc[mt][nb16*2+1], ah[mt], bh[2], bh[3]);
                    mmabf(acc[mt][nb16*2],   ah[mt], bl[0], bl[1]);
                    mmabf(acc[mt][nb16*2+1], ah[mt], bl[2], bl[3]);
                    mmabf(acc[mt][nb16*2],   al[mt], bh[0], bh[1]);
                    mmabf(acc[mt][nb16*2+1], al[mt], bh[2], bh[3]);
                }
            }
        }
        __syncthreads();
    }

#pragma unroll
    for (int mt = 0; mt < 4; mt++){
        int row  = mb*128 + wm*64 + mt*16 + gid;
        int row2 = row + 8;
#pragma unroll
        for (int nt = 0; nt < 4; nt++){
            int col = nb*128 + wn*32 + nt*8 + tig*2;
            float b0 = bias[col], b1 = bias[col+1];
            float v0 = acc[mt][nt][0] + b0, v1 = acc[mt][nt][1] + b1;
            float v2 = acc[mt][nt][2] + b0, v3 = acc[mt][nt][3] + b1;
            if (Cf){
                Cf[(size_t)row*DIMN + col]      = v0;
                Cf[(size_t)row*DIMN + col + 1]  = v1;
                Cf[(size_t)row2*DIMN + col]     = v2;
                Cf[(size_t)row2*DIMN + col + 1] = v3;
            } else {
                u32 h, l;
                split2(v0, v1, h, l);
                *(u32*)&Ch[(size_t)row*DIMN + col] = h;
                *(u32*)&Cl[(size_t)row*DIMN + col] = l;
                split2(v2, v3, h, l);
                *(u32*)&Ch[(size_t)row2*DIMN + col] = h;
                *(u32*)&Cl[(size_t)row2*DIMN + col] = l;
            }
        }
    }
}

// ---------------- flash attention, bf16 2-split ----------------
// 256 thr (8 warps), 128 queries/CTA, key tile 64, hd=64.
// smem/buffer: K[64 rows][256B: hi 8 ch | lo 8 ch], V same; swizzle chunk^=(row&7)
__global__ __launch_bounds__(256)
void attn_k(const u16* __restrict__ Qh, const u16* __restrict__ Ql,
            const u16* __restrict__ Kh, const u16* __restrict__ Kl,
            const u16* __restrict__ Vh, const u16* __restrict__ Vl,
            u16* __restrict__ Oh, u16* __restrict__ Ol)
{
    extern __shared__ char sm[];
    const u32 smBase = smaddr(sm);
    const int t = threadIdx.x;
    const int w = t >> 5, lane = t & 31, gid = lane >> 2, tig = lane & 3;
    const int qt = blockIdx.x, h = blockIdx.y, b = blockIdx.z;

    const size_t bsBase = (size_t)b * SEQ;
    const int hBase = h * HD;

    // Q fragments from gmem (bf16x2 u32 loads)
    const int r0 = qt*128 + w*16 + gid;
    u32 qh[4][4], ql[4][4];
    {
        const u16* ph = Qh + (bsBase + r0)*DIMN + hBase;
        const u16* pl = Ql + (bsBase + r0)*DIMN + hBase;
#pragma unroll
        for (int ks = 0; ks < 4; ks++){
            int c0 = ks*16 + tig*2;
            qh[ks][0] = *(const u32*)(ph + c0);
            qh[ks][1] = *(const u32*)(ph + 8*DIMN + c0);
            qh[ks][2] = *(const u32*)(ph + c0 + 8);
            qh[ks][3] = *(const u32*)(ph + 8*DIMN + c0 + 8);
            ql[ks][0] = *(const u32*)(pl + c0);
            ql[ks][1] = *(const u32*)(pl + 8*DIMN + c0);
            ql[ks][2] = *(const u32*)(pl + c0 + 8);
            ql[ks][3] = *(const u32*)(pl + 8*DIMN + c0 + 8);
        }
    }

    float oAcc[8][4];
#pragma unroll
    for (int i = 0; i < 8; i++)
#pragma unroll
        for (int r = 0; r < 4; r++) oAcc[i][r] = 0.f;
    float m0 = -1e30f, m1 = -1e30f, l0 = 0.f, l1 = 0.f;
    const float L2E = 1.4426950408889634f;

    auto loadTile = [&](int kt, int buf){
        u32 bufK = smBase + buf * 32768;
        u32 bufV = bufK + 16384;
#pragma unroll
        for (int j = 0; j < 4; j++){
            int id = t + 256*j;
            int row = id >> 4, c = id & 15;
            const u16* src = (c < 8 ? Kh : Kl) + (bsBase + kt*64 + row)*DIMN + hBase + (c&7)*8;
            cpa16(bufK + row*256 + ((c ^ (row&7)) << 4), src);
        }
#pragma unroll
        for (int j = 0; j < 4; j++){
            int id = t + 256*j;
            int row = id >> 4, c = id & 15;
            const u16* src = (c < 8 ? Vh : Vl) + (bsBase + kt*64 + row)*DIMN + hBase + (c&7)*8;
            cpa16(bufV + row*256 + ((c ^ (row&7)) << 4), src);
        }
    };

    loadTile(0, 0); cpcommit();

    for (int kt = 0; kt < SEQ/64; kt++){
        int buf = kt & 1;
        if (kt < SEQ/64 - 1){ loadTile(kt+1, buf^1); cpcommit(); cpwait1(); }
        else cpwait0();
        __syncthreads();

        u32 bufK = smBase + buf * 32768;
        u32 bufV = bufK + 16384;

        // ---- S = Q K^T ----
        float sAcc[8][4];
#pragma unroll
        for (int i = 0; i < 8; i++)
#pragma unroll
            for (int r = 0; r < 4; r++) sAcc[i][r] = 0.f;

#pragma unroll
        for (int j = 0; j < 4; j++){
#pragma unroll
            for (int ks = 0; ks < 4; ks++){
                u32 rowK = j*16 + ((lane >> 4) & 1)*8 + (lane & 7);
                u32 ck = ks*2 + ((lane >> 3) & 1);
                u32 bh[4], bl[4];
                ldsm4(bh, bufK + rowK*256 + ((ck ^ (rowK&7)) << 4));
                ldsm4(bl, bufK + rowK*256 + (((ck+8) ^ (rowK&7)) << 4));
                mmabf(sAcc[2*j],   qh[ks], bh[0], bh[1]);
                mmabf(sAcc[2*j+1], qh[ks], bh[2], bh[3]);
                mmabf(sAcc[2*j],   qh[ks], bl[0], bl[1]);
                mmabf(sAcc[2*j+1], qh[ks], bl[2], bl[3]);
                mmabf(sAcc[2*j],   ql[ks], bh[0], bh[1]);
                mmabf(sAcc[2*j+1], ql[ks], bh[2], bh[3]);
            }
        }

        // scale by 1/sqrt(64)
#pragma unroll
        for (int i = 0; i < 8; i++)
#pragma unroll
            for (int r = 0; r < 4; r++) sAcc[i][r] *= 0.125f;

        // ---- online softmax ----
        float rm0 = -1e30f, rm1 = -1e30f;
#pragma unroll
        for (int i = 0; i < 8; i++){
            rm0 = fmaxf(rm0, fmaxf(sAcc[i][0], sAcc[i][1]));
            rm1 = fmaxf(rm1, fmaxf(sAcc[i][2], sAcc[i][3]));
        }
        rm0 = fmaxf(rm0, __shfl_xor_sync(0xffffffffu, rm0, 1));
        rm0 = fmaxf(rm0, __shfl_xor_sync(0xffffffffu, rm0, 2));
        rm1 = fmaxf(rm1, __shfl_xor_sync(0xffffffffu, rm1, 1));
        rm1 = fmaxf(rm1, __shfl_xor_sync(0xffffffffu, rm1, 2));
        float m0n = fmaxf(m0, rm0), m1n = fmaxf(m1, rm1);
        float al0 = ex2f((m0 - m0n) * L2E);
        float al1 = ex2f((m1 - m1n) * L2E);
        m0 = m0n; m1 = m1n;

        float rs0 = 0.f, rs1 = 0.f;
#pragma unroll
        for (int i = 0; i < 8; i++){
            sAcc[i][0] = ex2f((sAcc[i][0] - m0) * L2E);
            sAcc[i][1] = ex2f((sAcc[i][1] - m0) * L2E);
            sAcc[i][2] = ex2f((sAcc[i][2] - m1) * L2E);
            sAcc[i][3] = ex2f((sAcc[i][3] - m1) * L2E);
            rs0 += sAcc[i][0] + sAcc[i][1];
            rs1 += sAcc[i][2] + sAcc[i][3];
        }
        rs0 += __shfl_xor_sync(0xffffffffu, rs0, 1);
        rs0 += __shfl_xor_sync(0xffffffffu, rs0, 2);
        rs1 += __shfl_xor_sync(0xffffffffu, rs1, 1);
        rs1 += __shfl_xor_sync(0xffffffffu, rs1, 2);
        l0 = l0 * al0 + rs0;
        l1 = l1 * al1 + rs1;
#pragma unroll
        for (int i = 0; i < 8; i++){
            oAcc[i][0] *= al0; oAcc[i][1] *= al0;
            oAcc[i][2] *= al1; oAcc[i][3] *= al1;
        }

        // ---- O += P V : S C-frags pack directly into A-frags ----
#pragma unroll
        for (int s = 0; s < 4; s++){
            u32 ph[4], pl[4];
            split2(sAcc[2*s][0],   sAcc[2*s][1],   ph[0], pl[0]);
            split2(sAcc[2*s][2],   sAcc[2*s][3],   ph[1], pl[1]);
            split2(sAcc[2*s+1][0], sAcc[2*s+1][1], ph[2], pl[2]);
            split2(sAcc[2*s+1][2], sAcc[2*s+1][3], ph[3], pl[3]);
#pragma unroll
            for (int j = 0; j < 4; j++){
                u32 rowV = s*16 + ((lane >> 3) & 1)*8 + (lane & 7);
                u32 cv = j*2 + ((lane >> 4) & 1);
                u32 bh[4], bl[4];
                ldsm4t(bh, bufV + rowV*256 + ((cv ^ (rowV&7)) << 4));
                ldsm4t(bl, bufV + rowV*256 + (((cv+8) ^ (rowV&7)) << 4));
                mmabf(oAcc[2*j],   ph, bh[0], bh[1]);
                mmabf(oAcc[2*j+1], ph, bh[2], bh[3]);
                mmabf(oAcc[2*j],   ph, bl[0], bl[1]);
                mmabf(oAcc[2*j+1], ph, bl[2], bl[3]);
                mmabf(oAcc[2*j],   pl, bh[0], bh[1]);
                mmabf(oAcc[2*j+1], pl, bh[2], bh[3]);
            }
        }
        __syncthreads();
    }

    // epilogue: normalize, split, store hi/lo
    const float inv0 = 1.f / l0, inv1 = 1.f / l1;
    u16* po_h = Oh + (bsBase + r0)*DIMN + hBase;
    u16* po_l = Ol + (bsBase + r0)*DIMN + hBase;
#pragma unroll
    for (int nt = 0; nt < 8; nt++){
        int col = nt*8 + tig*2;
        u32 hh, ll;
        split2(oAcc[nt][0]*inv0, oAcc[nt][1]*inv0, hh, ll);
        *(u32*)(po_h + col) = hh;
        *(u32*)(po_l + col) = ll;
        split2(oAcc[nt][2]*inv1, oAcc[nt][3]*inv1, hh, ll);
        *(u32*)(po_h + 8*DIMN + col) = hh;
        *(u32*)(po_l + 8*DIMN + col) = ll;
    }
}

// ---------------- launch ----------------
extern "C" void kernel_launch(void* const* d_in, const int* in_sizes, int n_in,
                              void* d_out, int out_size)
{
    const float* Q  = (const float*)d_in[0];
    const float* K  = (const float*)d_in[1];
    const float* V  = (const float*)d_in[2];
    const float* Wq = (const float*)d_in[3];
    const float* bq = (const float*)d_in[4];
    const float* Wk = (const float*)d_in[5];
    const float* bk = (const float*)d_in[6];
    const float* Wv = (const float*)d_in[7];
    const float* bv = (const float*)d_in[8];
    const float* Wo = (const float*)d_in[9];
    const float* bo = (const float*)d_in[10];
    float* out = (float*)d_out;

    static bool attrSet = false;
    if (!attrSet){
        cudaFuncSetAttribute(gemm_bias_k, cudaFuncAttributeMaxDynamicSharedMemorySize, 65536);
        cudaFuncSetAttribute(attn_k,      cudaFuncAttributeMaxDynamicSharedMemorySize, 65536);
        attrSet = true;
    }

    u16 *iQh, *iQl, *iKh, *iKl, *iVh, *iVl;
    u16 *wqh, *wql, *wkh, *wkl, *wvh, *wvl, *woh, *wol;
    u16 *pqh, *pql, *pkh, *pkl, *pvh, *pvl, *oh, *ol;
    cudaGetSymbolAddress((void**)&iQh, inQh); cudaGetSymbolAddress((void**)&iQl, inQl);
    cudaGetSymbolAddress((void**)&iKh, inKh); cudaGetSymbolAddress((void**)&iKl, inKl);
    cudaGetSymbolAddress((void**)&iVh, inVh); cudaGetSymbolAddress((void**)&iVl, inVl);
    cudaGetSymbolAddress((void**)&wqh, wQh);  cudaGetSymbolAddress((void**)&wql, wQl);
    cudaGetSymbolAddress((void**)&wkh, wKh);  cudaGetSymbolAddress((void**)&wkl, wKl);
    cudaGetSymbolAddress((void**)&wvh, wVh);  cudaGetSymbolAddress((void**)&wvl, wVl);
    cudaGetSymbolAddress((void**)&woh, wOh);  cudaGetSymbolAddress((void**)&wol, wOl);
    cudaGetSymbolAddress((void**)&pqh, pjQh); cudaGetSymbolAddress((void**)&pql, pjQl);
    cudaGetSymbolAddress((void**)&pkh, pjKh); cudaGetSymbolAddress((void**)&pkl, pjKl);
    cudaGetSymbolAddress((void**)&pvh, pjVh); cudaGetSymbolAddress((void**)&pvl, pjVl);
    cudaGetSymbolAddress((void**)&oh, aOh);   cudaGetSymbolAddress((void**)&ol, aOl);

    const int n4in = (int)(NELEM/4), n4w = (int)(WELEM/4);
    split_k<<<(n4in+255)/256, 256>>>(Q,  iQh, iQl, n4in);
    split_k<<<(n4in+255)/256, 256>>>(K,  iKh, iKl, n4in);
    split_k<<<(n4in+255)/256, 256>>>(V,  iVh, iVl, n4in);
    split_k<<<(n4w +255)/256, 256>>>(Wq, wqh, wql, n4w);
    split_k<<<(n4w +255)/256, 256>>>(Wk, wkh, wkl, n4w);
    split_k<<<(n4w +255)/256, 256>>>(Wv, wvh, wvl, n4w);
    split_k<<<(n4w +255)/256, 256>>>(Wo, woh, wol, n4w);

    dim3 gg(DIMN/128, MTOT/128);
    gemm_bias_k<<<gg, 256, 65536>>>(iQh, iQl, wqh, wql, bq, pqh, pql, nullptr);
    gemm_bias_k<<<gg, 256, 65536>>>(iKh, iKl, wkh, wkl, bk, pkh, pkl, nullptr);
    gemm_bias_k<<<gg, 256, 65536>>>(iVh, iVl, wvh, wvl, bv, pvh, pvl, nullptr);

    attn_k<<<dim3(SEQ/128, HEADS, BATCH), 256, 65536>>>(pqh, pql, pkh, pkl, pvh, pvl, oh, ol);

    gemm_bias_k<<<gg, 256, 65536>>>(oh, ol, woh, wol, bo, nullptr, nullptr, out);
}